// round 1
// baseline (speedup 1.0000x reference)
#include <cuda_runtime.h>

// Problem constants (fixed shapes per reference setup_inputs)
#define BV 4
#define CV 1024
#define HV 64
#define WV 64
#define SV (HV*WV)          // 4096 spatial positions
#define AHV 7
#define AWV 7
#define NBINS (AHV*AWV)     // 49
#define CCHUNK 128          // channels per block
#define SPATIAL_SCALE 0.0625f

// Scratch: features transposed to [B, H, W, C] so channel gathers coalesce.
// 4*64*64*1024 floats = 64 MiB static device allocation (allowed scratch).
__device__ float g_feat_t[(size_t)BV * HV * WV * CV];

// ---------------------------------------------------------------------------
// Pass 1: transpose [B, C, H*W] -> [B, H*W, C] with 32x32 smem tiles.
// Both global reads and writes are fully coalesced.
// ---------------------------------------------------------------------------
__global__ void transpose_kernel(const float* __restrict__ in) {
    __shared__ float tile[32][33];
    const int b  = blockIdx.z;
    const int s0 = blockIdx.x * 32;   // spatial tile origin
    const int c0 = blockIdx.y * 32;   // channel tile origin
    const int tx = threadIdx.x;
    const int ty = threadIdx.y;

    const float* src = in + (size_t)b * CV * SV;
    float* dst = g_feat_t + (size_t)b * SV * CV;

    #pragma unroll
    for (int j = 0; j < 32; j += 8)
        tile[ty + j][tx] = src[(size_t)(c0 + ty + j) * SV + (s0 + tx)];

    __syncthreads();

    #pragma unroll
    for (int j = 0; j < 32; j += 8)
        dst[(size_t)(s0 + ty + j) * CV + (c0 + tx)] = tile[tx][ty + j];
}

// ---------------------------------------------------------------------------
// Pass 2: RoIAlign gather + bilerp.
// Block = (one roi, 128 consecutive channels). Bin params shared in smem.
// Gathers are 128B warp-coalesced lines from the [B,H,W,C] scratch.
// Results staged in smem, then streamed out as aligned float4 (coalesced).
// ---------------------------------------------------------------------------
__global__ __launch_bounds__(CCHUNK)
void roialign_kernel(const float* __restrict__ rois, float* __restrict__ out) {
    __shared__ int   sb_base[NBINS];
    __shared__ float sb_hr[NBINS];
    __shared__ float sb_wr[NBINS];
    __shared__ float sb_valid[NBINS];
    __shared__ float stage[CCHUNK * NBINS];   // 25088 B

    const int n   = blockIdx.y;
    const int c0  = blockIdx.x * CCHUNK;
    const int tid = threadIdx.x;

    if (tid < NBINS) {
        const float* r = rois + (size_t)n * 5;
        const int   bi = (int)r[0];
        const float x1 = r[1] * SPATIAL_SCALE;
        const float y1 = r[2] * SPATIAL_SCALE;
        const float x2 = r[3] * SPATIAL_SCALE;
        const float y2 = r[4] * SPATIAL_SCALE;
        const float bin_w = fmaxf(x2 - x1, 0.0f) / (float)(AWV - 1);
        const float bin_h = fmaxf(y2 - y1, 0.0f) / (float)(AHV - 1);

        const int ph = tid / AWV;
        const int pw = tid % AWV;
        const float h = y1 + (float)ph * bin_h;
        const float w = x1 + (float)pw * bin_w;

        const float hstart = fminf(floorf(h), (float)(HV - 2));
        const float wstart = fminf(floorf(w), (float)(WV - 2));
        const float hr = h - hstart;   // may exceed 1 near boundary (matches ref)
        const float wr = w - wstart;

        const int hs = min(max((int)hstart, 0), HV - 2);
        const int ws = min(max((int)wstart, 0), WV - 2);
        const bool v = (h >= 0.0f) && (h < (float)HV) &&
                       (w >= 0.0f) && (w < (float)WV);

        sb_base[tid]  = ((bi * HV + hs) * WV + ws) * CV + c0;
        sb_hr[tid]    = hr;
        sb_wr[tid]    = wr;
        sb_valid[tid] = v ? 1.0f : 0.0f;
    }
    __syncthreads();

    const float* __restrict__ f = g_feat_t;

    #pragma unroll 7
    for (int j = 0; j < NBINS; ++j) {
        const int off = sb_base[j] + tid;
        const float ul = __ldg(f + off);
        const float ur = __ldg(f + off + CV);            // w+1
        const float dl = __ldg(f + off + WV * CV);       // h+1
        const float dr = __ldg(f + off + WV * CV + CV);  // h+1, w+1
        const float hr = sb_hr[j];
        const float wr = sb_wr[j];
        const float top = ul + wr * (ur - ul);
        const float bot = dl + wr * (dr - dl);
        // stride 49 between threads: 49 % 32 = 17 (odd) -> conflict-free STS
        stage[tid * NBINS + j] = (top + hr * (bot - top)) * sb_valid[j];
    }
    __syncthreads();

    // Coalesced float4 writeback. Base offset (n*CV + c0)*49*4 B is 16B-aligned
    // because c0 is a multiple of 128 (49*4*128 % 16 == 0).
    float4* __restrict__ o4 = (float4*)(out + ((size_t)n * CV + c0) * NBINS);
    const float4* __restrict__ s4 = (const float4*)stage;
    #pragma unroll
    for (int i = tid; i < (CCHUNK * NBINS) / 4; i += CCHUNK)
        o4[i] = s4[i];
}

// ---------------------------------------------------------------------------
extern "C" void kernel_launch(void* const* d_in, const int* in_sizes, int n_in,
                              void* d_out, int out_size) {
    const float* features = (const float*)d_in[0];
    const float* rois     = (const float*)d_in[1];
    float* out            = (float*)d_out;

    const int N = in_sizes[1] / 5;   // 2048 rois

    dim3 tgrid(SV / 32, CV / 32, BV);   // (128, 32, 4)
    transpose_kernel<<<tgrid, dim3(32, 8)>>>(features);

    dim3 grid(CV / CCHUNK, N);          // (8, 2048)
    roialign_kernel<<<grid, CCHUNK>>>(rois, out);
}

// round 3
// speedup vs baseline: 1.3113x; 1.3113x over previous
#include <cuda_runtime.h>

// Problem constants (fixed shapes per reference setup_inputs)
#define BV 4
#define CV 1024
#define HV 64
#define WV 64
#define SV (HV*WV)          // 4096 spatial positions
#define AHV 7
#define AWV 7
#define NBINS (AHV*AWV)     // 49
#define CCHUNK 64           // channels per block
#define BSPLIT 25           // bins [0,25) for half 0, [25,49) for half 1
#define SPATIAL_SCALE 0.0625f

// Scratch: features transposed to [B, H, W, C] so channel gathers coalesce.
// 4*64*64*1024 floats = 64 MiB static device allocation (allowed scratch).
__device__ float g_feat_t[(size_t)BV * HV * WV * CV];

// ---------------------------------------------------------------------------
// Pass 1: transpose [B, C, H*W] -> [B, H*W, C] with 32x32 smem tiles.
// ---------------------------------------------------------------------------
__global__ void transpose_kernel(const float* __restrict__ in) {
    __shared__ float tile[32][33];
    const int b  = blockIdx.z;
    const int s0 = blockIdx.x * 32;   // spatial tile origin
    const int c0 = blockIdx.y * 32;   // channel tile origin
    const int tx = threadIdx.x;
    const int ty = threadIdx.y;

    const float* src = in + (size_t)b * CV * SV;
    float* dst = g_feat_t + (size_t)b * SV * CV;

    #pragma unroll
    for (int j = 0; j < 32; j += 8)
        tile[ty + j][tx] = src[(size_t)(c0 + ty + j) * SV + (s0 + tx)];

    __syncthreads();

    #pragma unroll
    for (int j = 0; j < 32; j += 8)
        dst[(size_t)(s0 + ty + j) * CV + (c0 + tx)] = tile[tx][ty + j];
}

// ---------------------------------------------------------------------------
// Bin processing helper: fully unrolled so ptxas batches independent LDGs.
// sp[j] = { base_offset_as_float_bits, hr, wr, valid }
// Corner loads use immediate offsets off one base register.
// ---------------------------------------------------------------------------
template<int J0, int J1>
__device__ __forceinline__ void process_bins(const float4* __restrict__ sp,
                                             const float*  __restrict__ f,
                                             int cch, float* __restrict__ stage) {
    #pragma unroll
    for (int j = J0; j < J1; ++j) {
        const float4 p  = sp[j];
        const int    off = __float_as_int(p.x) + cch;
        const float ul = __ldg(f + off);
        const float ur = __ldg(f + off + CV);            // w+1
        const float dl = __ldg(f + off + WV * CV);       // h+1
        const float dr = __ldg(f + off + WV * CV + CV);  // h+1, w+1
        const float top = fmaf(p.z, ur - ul, ul);
        const float bot = fmaf(p.z, dr - dl, dl);
        // stride 49 across lanes (odd mod 32) -> conflict-free STS
        stage[cch * NBINS + j] = fmaf(p.y, bot - top, top) * p.w;
    }
}

// ---------------------------------------------------------------------------
// Pass 2: RoIAlign gather + bilerp.
// Block = 128 threads: 64 consecutive channels of one roi, bins split in two
// halves across tid/64. Staged result is a CONTIGUOUS 64x49-float output slab
// -> perfectly coalesced float4 writeback (1.0x write amplification).
// ---------------------------------------------------------------------------
__global__ __launch_bounds__(128, 10)
void roialign_kernel(const float* __restrict__ rois, float* __restrict__ out) {
    __shared__ float4 sp[NBINS];              // per-bin packed params
    __shared__ float  stage[CCHUNK * NBINS];  // 12544 B, == output layout

    const int n   = blockIdx.y;
    const int c0  = blockIdx.x * CCHUNK;
    const int tid = threadIdx.x;

    if (tid < NBINS) {
        const float* r = rois + (size_t)n * 5;
        const int   bi = (int)r[0];
        const float x1 = r[1] * SPATIAL_SCALE;
        const float y1 = r[2] * SPATIAL_SCALE;
        const float x2 = r[3] * SPATIAL_SCALE;
        const float y2 = r[4] * SPATIAL_SCALE;
        const float bin_w = fmaxf(x2 - x1, 0.0f) / (float)(AWV - 1);
        const float bin_h = fmaxf(y2 - y1, 0.0f) / (float)(AHV - 1);

        const int ph = tid / AWV;
        const int pw = tid % AWV;
        const float h = y1 + (float)ph * bin_h;
        const float w = x1 + (float)pw * bin_w;

        const float hstart = fminf(floorf(h), (float)(HV - 2));
        const float wstart = fminf(floorf(w), (float)(WV - 2));
        const float hr = h - hstart;   // may exceed 1 near boundary (matches ref)
        const float wr = w - wstart;

        const int hs = min(max((int)hstart, 0), HV - 2);
        const int ws = min(max((int)wstart, 0), WV - 2);
        const bool v = (h >= 0.0f) && (h < (float)HV) &&
                       (w >= 0.0f) && (w < (float)WV);

        const int base = ((bi * HV + hs) * WV + ws) * CV + c0;
        sp[tid] = make_float4(__int_as_float(base), hr, wr, v ? 1.0f : 0.0f);
    }
    __syncthreads();

    const int cch = tid & (CCHUNK - 1);
    const float* __restrict__ f = g_feat_t;

    if (tid < CCHUNK) process_bins<0, BSPLIT>(sp, f, cch, stage);
    else              process_bins<BSPLIT, NBINS>(sp, f, cch, stage);
    __syncthreads();

    // Coalesced float4 writeback: stage is exactly the contiguous output slab
    // for channels [c0, c0+64). Base (n*CV+c0)*49*4B: c0 mult of 64 ->
    // 64*196 = 12544 B, 16B-aligned. 12544 B = 784 float4.
    float4* __restrict__ o4 = (float4*)(out + ((size_t)n * CV + c0) * NBINS);
    const float4* __restrict__ s4 = (const float4*)stage;
    #pragma unroll
    for (int i = tid; i < (CCHUNK * NBINS) / 4; i += 128)
        o4[i] = s4[i];
}

// ---------------------------------------------------------------------------
extern "C" void kernel_launch(void* const* d_in, const int* in_sizes, int n_in,
                              void* d_out, int out_size) {
    const float* features = (const float*)d_in[0];
    const float* rois     = (const float*)d_in[1];
    float* out            = (float*)d_out;

    const int N = in_sizes[1] / 5;   // 2048 rois

    dim3 tgrid(SV / 32, CV / 32, BV);   // (128, 32, 4)
    transpose_kernel<<<tgrid, dim3(32, 8)>>>(features);

    dim3 grid(CV / CCHUNK, N);          // (16, 2048)
    roialign_kernel<<<grid, 128>>>(rois, out);
}

// round 7
// speedup vs baseline: 1.9972x; 1.5231x over previous
#include <cuda_runtime.h>

// Problem constants (fixed shapes per reference setup_inputs)
#define BV 4
#define CV 1024
#define HV 64
#define WV 64
#define SV (HV*WV)          // 4096 spatial positions
#define AHV 7
#define AWV 7
#define NBINS (AHV*AWV)     // 49
#define CGRP 128            // channels per block (one permuted group)
#define SPATIAL_SCALE 0.0625f

// Scratch: features as [B, H, W, C'] where C' is permuted within each
// 128-channel group: position p holds channel (p%4)*32 + p/4, i.e. the
// float4 at lane L contains channels {L, L+32, L+64, L+96}.
// 64 MiB static device allocation (allowed scratch).
__device__ float g_feat_t[(size_t)BV * HV * WV * CV];

// ---------------------------------------------------------------------------
// Pass 1: transpose+permute [B, C, H*W] -> [B, H*W, C_perm].
// Tile: 128 channels x 32 spatial. Reads and writes fully coalesced
// (writes are STG.128 of the 4-channel quads).
// ---------------------------------------------------------------------------
__global__ __launch_bounds__(256)
void transpose_kernel(const float* __restrict__ in) {
    __shared__ float tile[CGRP][33];
    const int b  = blockIdx.z;
    const int s0 = blockIdx.x * 32;    // spatial tile origin
    const int c0 = blockIdx.y * CGRP;  // channel group origin
    const int tx = threadIdx.x;        // 0..31
    const int ty = threadIdx.y;        // 0..7

    const float* src = in + (size_t)b * CV * SV;
    float* dst = g_feat_t + (size_t)b * SV * CV;

    #pragma unroll
    for (int cc = 0; cc < CGRP; cc += 8)
        tile[cc + ty][tx] = src[(size_t)(c0 + cc + ty) * SV + (s0 + tx)];

    __syncthreads();

    // Write: lane tx emits the quad {tx, tx+32, tx+64, tx+96} for spatial s.
    // LDS lane-stride 33 -> conflict-free; STG.128 x 32 lanes = 512B contig.
    #pragma unroll
    for (int s = ty; s < 32; s += 8) {
        float4 v;
        v.x = tile[tx      ][s];
        v.y = tile[tx + 32 ][s];
        v.z = tile[tx + 64 ][s];
        v.w = tile[tx + 96 ][s];
        *(float4*)(dst + (size_t)(s0 + s) * CV + c0 + 4 * tx) = v;
    }
}

// ---------------------------------------------------------------------------
// Pass 2: RoIAlign gather + bilerp.
// Block = 256 threads (8 warps) over 128 channels of one roi.
// Warp w handles bins j = w, w+8, ... Each lane gathers float4 (4 channels)
// per corner -> LDG.128, 64B in flight per bin per thread.
// Results staged in true-channel-order [c][49] (conflict-free scalar STS,
// bank = 17*lane + const), then streamed out as contiguous float4 slab.
// ---------------------------------------------------------------------------
__global__ __launch_bounds__(256, 6)
void roialign_kernel(const float* __restrict__ rois, float* __restrict__ out) {
    __shared__ float4 sp[NBINS];             // { base_bits, hr, wr, valid }
    __shared__ float  stage[CGRP * NBINS];   // 25088 B == output slab

    const int n    = blockIdx.y;
    const int c0   = blockIdx.x * CGRP;
    const int tid  = threadIdx.x;
    const int w    = tid >> 5;               // warp 0..7
    const int lane = tid & 31;

    if (tid < NBINS) {
        const float* r = rois + (size_t)n * 5;
        const int   bi = (int)r[0];
        const float x1 = r[1] * SPATIAL_SCALE;
        const float y1 = r[2] * SPATIAL_SCALE;
        const float x2 = r[3] * SPATIAL_SCALE;
        const float y2 = r[4] * SPATIAL_SCALE;
        const float bin_w = fmaxf(x2 - x1, 0.0f) / (float)(AWV - 1);
        const float bin_h = fmaxf(y2 - y1, 0.0f) / (float)(AHV - 1);

        const int ph = tid / AWV;
        const int pw = tid % AWV;
        const float h = y1 + (float)ph * bin_h;
        const float wq = x1 + (float)pw * bin_w;

        const float hstart = fminf(floorf(h),  (float)(HV - 2));
        const float wstart = fminf(floorf(wq), (float)(WV - 2));
        const float hr = h - hstart;    // may exceed 1 near boundary (matches ref)
        const float wr = wq - wstart;

        const int hs = min(max((int)hstart, 0), HV - 2);
        const int ws = min(max((int)wstart, 0), WV - 2);
        const bool v = (h >= 0.0f) && (h < (float)HV) &&
                       (wq >= 0.0f) && (wq < (float)WV);

        const int base = ((bi * HV + hs) * WV + ws) * CV + c0;
        sp[tid] = make_float4(__int_as_float(base), hr, wr, v ? 1.0f : 0.0f);
    }
    __syncthreads();

    const float* __restrict__ f = g_feat_t;

    #pragma unroll 7
    for (int j = w; j < NBINS; j += 8) {
        const float4 p   = sp[j];
        const int    off = __float_as_int(p.x) + 4 * lane;
        const float4 ul = *(const float4*)(f + off);
        const float4 ur = *(const float4*)(f + off + CV);            // w+1
        const float4 dl = *(const float4*)(f + off + WV * CV);       // h+1
        const float4 dr = *(const float4*)(f + off + WV * CV + CV);  // h+1, w+1
        const float hr = p.y, wr = p.z, vv = p.w;

        float t, bo;
        t  = fmaf(wr, ur.x - ul.x, ul.x);
        bo = fmaf(wr, dr.x - dl.x, dl.x);
        stage[(lane      ) * NBINS + j] = fmaf(hr, bo - t, t) * vv;  // chan lane
        t  = fmaf(wr, ur.y - ul.y, ul.y);
        bo = fmaf(wr, dr.y - dl.y, dl.y);
        stage[(lane + 32 ) * NBINS + j] = fmaf(hr, bo - t, t) * vv;  // chan lane+32
        t  = fmaf(wr, ur.z - ul.z, ul.z);
        bo = fmaf(wr, dr.z - dl.z, dl.z);
        stage[(lane + 64 ) * NBINS + j] = fmaf(hr, bo - t, t) * vv;  // chan lane+64
        t  = fmaf(wr, ur.w - ul.w, ul.w);
        bo = fmaf(wr, dr.w - dl.w, dl.w);
        stage[(lane + 96 ) * NBINS + j] = fmaf(hr, bo - t, t) * vv;  // chan lane+96
    }
    __syncthreads();

    // Coalesced float4 writeback: stage is exactly the contiguous output slab
    // for channels [c0, c0+128). 128*49 floats = 1568 float4.
    float4* __restrict__ o4 = (float4*)(out + ((size_t)n * CV + c0) * NBINS);
    const float4* __restrict__ s4 = (const float4*)stage;
    #pragma unroll
    for (int i = tid; i < (CGRP * NBINS) / 4; i += 256)
        o4[i] = s4[i];
}

// ---------------------------------------------------------------------------
extern "C" void kernel_launch(void* const* d_in, const int* in_sizes, int n_in,
                              void* d_out, int out_size) {
    const float* features = (const float*)d_in[0];
    const float* rois     = (const float*)d_in[1];
    float* out            = (float*)d_out;

    const int N = in_sizes[1] / 5;   // 2048 rois

    dim3 tgrid(SV / 32, CV / CGRP, BV);   // (128, 8, 4)
    transpose_kernel<<<tgrid, dim3(32, 8)>>>(features);

    dim3 grid(CV / CGRP, N);              // (8, 2048)
    roialign_kernel<<<grid, 256>>>(rois, out);
}